// round 16
// baseline (speedup 1.0000x reference)
#include <cuda_runtime.h>
#include <cuda.h>
#include <cuda_bf16.h>
#include <math.h>
#include <stdint.h>

#if defined(__CUDA_ARCH__) && defined(__CUDA_ARCH_FEAT_SM103_ALL)
#define HAS_TC 1
#else
#define HAS_TC 0
#endif

// ---------------- scratch ----------------
static __device__ float g_y66[8 * 512 * 66 * 66];                      // conv output 71.4 MB
static __device__ __align__(1024) uint16_t g_xta_h[64 * 4624 * 64];    // [b*8+icb][pix68][64ic] hi bf16
static __device__ __align__(1024) uint16_t g_xta_l[64 * 4624 * 64];    // lo bf16
static __device__ __align__(1024) uint16_t g_bswh[72 * 512 * 64];      // weights pre-swizzled, pos-major k, hi
static __device__ __align__(1024) uint16_t g_bswl[72 * 512 * 64];      // lo
static __device__ float g_partials[2048];
static __device__ float g_inv[1];
static __device__ float g_styles[8 * 512];
static __device__ float g_mult[8 * 512];
static __device__ float g_S[512 * 512];
static __device__ float g_demod[8 * 512];

// ---------------- PTX helpers ----------------
__device__ __forceinline__ uint32_t smem_u32(const void* p) {
    uint32_t a;
    asm("{ .reg .u64 t; cvta.to.shared.u64 t, %1; cvt.u32.u64 %0, t; }" : "=r"(a) : "l"(p));
    return a;
}
__device__ __forceinline__ uint32_t elect_one() {
    uint32_t p;
    asm volatile("{\n\t.reg .pred p;\n\telect.sync _|p, 0xFFFFFFFF;\n\tselp.b32 %0, 1, 0, p;\n\t}" : "=r"(p));
    return p;
}
__device__ __forceinline__ uint32_t cluster_rank() {
    uint32_t r;
    asm("mov.u32 %0, %%cluster_ctarank;" : "=r"(r));
    return r;
}
#define MBAR_INIT(mb, c)  asm volatile("mbarrier.init.shared.b64 [%0], %1;" :: "r"(mb), "r"(c) : "memory")
#define FENCE_ASYNC()     asm volatile("fence.proxy.async.shared::cta;" ::: "memory")
#define MBAR_EXPECT_TX(mb, bytes) \
    asm volatile("mbarrier.arrive.expect_tx.shared.b64 _, [%0], %1;" :: "r"(mb), "r"(bytes) : "memory")
#define CLUSTER_SYNC() do { \
    asm volatile("barrier.cluster.arrive.aligned;" ::: "memory"); \
    asm volatile("barrier.cluster.wait.aligned;" ::: "memory"); } while (0)

__device__ __forceinline__ void mbar_wait(uint32_t mb, uint32_t parity) {
    uint32_t done;
    asm volatile("{\n\t.reg .pred p;\n\tmbarrier.try_wait.parity.acquire.cta.shared::cta.b64 p, [%1], %2;\n\tselp.b32 %0, 1, 0, p;\n\t}"
                 : "=r"(done) : "r"(mb), "r"(parity) : "memory");
    if (!done) {
        asm volatile("{\n\t.reg .pred P1;\n\tWL_%=:\n\tmbarrier.try_wait.parity.acquire.cta.shared::cta.b64 P1, [%0], %1, 0x989680;\n\t@P1 bra.uni WD_%=;\n\tbra.uni WL_%=;\n\tWD_%=:\n\t}"
                     :: "r"(mb), "r"(parity) : "memory");
    }
}

// packed fp32x2 FMA (fallback path)
__device__ __forceinline__ void fma2(unsigned long long& d, unsigned long long a, unsigned long long b) {
    asm("fma.rn.f32x2 %0, %1, %2, %0;" : "+l"(d) : "l"(a), "l"(b));
}

#if HAS_TC
#define TC_ALLOC_CG2(sm, n)   asm volatile("tcgen05.alloc.cta_group::2.sync.aligned.shared::cta.b32 [%0], %1;" :: "r"(sm), "r"(n) : "memory")
#define TC_DEALLOC_CG2(t, n)  asm volatile("tcgen05.dealloc.cta_group::2.sync.aligned.b32 %0, %1;" :: "r"(t), "r"(n))
#define TC_RELINQ_CG2()       asm volatile("tcgen05.relinquish_alloc_permit.cta_group::2.sync.aligned;")
#define TC_COMMIT_CG2_MC(mb, mask) \
    asm volatile("tcgen05.commit.cta_group::2.mbarrier::arrive::one.shared::cluster.multicast::cluster.b64 [%0], %1;" \
                 :: "r"(mb), "h"((uint16_t)(mask)) : "memory")
#define TC_FENCE_AFTER()  asm volatile("tcgen05.fence::after_thread_sync;" ::: "memory")
#define TC_FENCE_BEFORE() asm volatile("tcgen05.fence::before_thread_sync;" ::: "memory")
#define TC_WAIT_LD()      asm volatile("tcgen05.wait::ld.sync.aligned;" ::: "memory")
// cg2 bf16 SS MMA: M=256 across CTA pair; 8-reg disable mask (all zero)
__device__ __forceinline__ void mma_f16_ss_cg2(uint32_t d, uint64_t a, uint64_t b, uint32_t idesc, uint32_t en) {
    asm volatile("{\n\t.reg .pred p;\n\tsetp.ne.u32 p, %4, 0;\n\t"
                 "tcgen05.mma.cta_group::2.kind::f16 [%0], %1, %2, %3, {%5,%5,%5,%5,%5,%5,%5,%5}, p;\n\t}"
                 :: "r"(d), "l"(a), "l"(b), "r"(idesc), "r"(en), "r"(0u) : "memory");
}
// cg2 TMA: both CTAs execute; complete_tx targets leader CTA's barrier (clear bit 24)
__device__ __forceinline__ void tma2d_cg2(uint32_t dst, const void* map, int x, int y, uint32_t mbar) {
    asm volatile("{\n\t.reg .b32 lb;\n\tand.b32 lb, %4, 0xFEFFFFFF;\n\t"
                 "cp.async.bulk.tensor.2d.cta_group::2.shared::cluster.global.tile.mbarrier::complete_tx::bytes "
                 "[%0], [%1, {%2, %3}], [lb];\n\t}"
                 :: "r"(dst), "l"(map), "r"(x), "r"(y), "r"(mbar) : "memory");
}
#endif

// SW128 K-major descriptor base: layout=2, version=1, SBO=64, LBO=1
__device__ __forceinline__ uint64_t mk_desc(uint32_t addr) {
    return ((uint64_t)2 << 61) | ((uint64_t)1 << 46) | ((uint64_t)64 << 32) | ((uint64_t)1 << 16)
         | (uint64_t)((addr >> 4) & 0x3FFF);
}
// idesc kind::f16: F32 accum | A=BF16 | B=BF16 | N=256 | M=256 (cg2)
#define IDESC_M256_N256 ((1u<<4) | (1u<<7) | (1u<<10) | (32u<<17) | (16u<<24))

// ---------------- small prep kernels ----------------
__global__ void __launch_bounds__(256) k_reduce(const float* __restrict__ x, int n) {
    float s = 0.f;
    for (int i = blockIdx.x * blockDim.x + threadIdx.x; i < n; i += gridDim.x * blockDim.x) {
        float v = x[i]; s += v * v;
    }
    __shared__ float sm[256];
    sm[threadIdx.x] = s; __syncthreads();
    for (int o = 128; o > 0; o >>= 1) { if (threadIdx.x < o) sm[threadIdx.x] += sm[threadIdx.x + o]; __syncthreads(); }
    if (threadIdx.x == 0) g_partials[blockIdx.x] = sm[0];
}
__global__ void __launch_bounds__(1024) k_finalize(const float* __restrict__ w_avg, float inv_n) {
    __shared__ float sm[1024];
    float s = 0.f;
    for (int i = threadIdx.x; i < 2048; i += 1024) s += g_partials[i];
    sm[threadIdx.x] = s; __syncthreads();
    for (int o = 512; o > 0; o >>= 1) { if (threadIdx.x < o) sm[threadIdx.x] += sm[threadIdx.x + o]; __syncthreads(); }
    if (threadIdx.x == 0) {
        float mag = sm[0] * inv_n;
        float wn  = mag + 0.999f * (w_avg[0] - mag);
        g_inv[0]  = rsqrtf(wn);
    }
}
__global__ void __launch_bounds__(256) k_styles(const float* __restrict__ w, const float* __restrict__ aw,
                                                const float* __restrict__ ab) {
    int idx = blockIdx.x * 256 + threadIdx.x;
    int b = idx >> 9, i = idx & 511;
    const float* wr = w + b * 512;
    const float* ar = aw + i * 512;
    float s = 0.f;
    for (int j = 0; j < 512; j++) s += wr[j] * ar[j];
    s = s * 0.04419417382415922f + ab[i];
    g_styles[idx] = s;
    g_mult[idx]   = s * g_inv[0];
}
__global__ void __launch_bounds__(256) k_S(const float* __restrict__ cw) {
    int idx = blockIdx.x * 256 + threadIdx.x;
    const float* p = cw + (size_t)idx * 9;
    float s = 0.f;
#pragma unroll
    for (int k = 0; k < 9; k++) s += p[k] * p[k];
    g_S[idx] = s;
}
__global__ void __launch_bounds__(256) k_demod() {
    int idx = blockIdx.x * 256 + threadIdx.x;
    int b = idx >> 9, o = idx & 511;
    const float* st = g_styles + b * 512;
    const float* Sr = g_S + o * 512;
    float s = 0.f;
    for (int i = 0; i < 512; i++) { float t = st[i]; s += t * t * Sr[i]; }
    g_demod[idx] = rsqrtf(s + 1e-8f);
}

// zero the 2-pixel borders of all 64 [pix][64ic] planes
__global__ void __launch_bounds__(64) k_zero_border() {
    int pix = blockIdx.x, b = blockIdx.y;
    int pr = pix / 68, pc = pix % 68;
    if (pr >= 2 && pr < 66 && pc >= 2 && pc < 66) return;
    int icb = threadIdx.x >> 3, seg = threadIdx.x & 7;
    size_t off = (((size_t)(b * 8 + icb) * 4624 + pix) << 6) + seg * 8;
    int4 z = make_int4(0, 0, 0, 0);
    *(int4*)(g_xta_h + off) = z;
    *(int4*)(g_xta_l + off) = z;
}

// transpose + scale + split into [b*8+icb][pix][64ic] hi/lo planes
__global__ void __launch_bounds__(256) k_transpose(const float* __restrict__ x) {
    __shared__ uint32_t sp[128][65];
    const int b = blockIdx.z, gr = blockIdx.y, ic0 = blockIdx.x << 7;
    const int tid = threadIdx.x;
    const float* mb = g_mult + b * 512 + ic0;
    const float* xb = x + (((size_t)(b * 512 + ic0)) << 12) + (gr << 6);
#pragma unroll
    for (int it = 0; it < 32; it++) {
        int idx = it * 256 + tid;
        int icl = idx >> 6, gc = idx & 63;
        float v = xb[((size_t)icl << 12) + gc] * mb[icl];
        __nv_bfloat16 h = __float2bfloat16(v);
        float hf = __bfloat162float(h);
        __nv_bfloat16 l = __float2bfloat16(v - hf);
        sp[icl][gc] = (uint32_t)__bfloat16_as_ushort(h) | ((uint32_t)__bfloat16_as_ushort(l) << 16);
    }
    __syncthreads();
#pragma unroll
    for (int it = 0; it < 4; it++) {
        int idx = it * 256 + tid;
        int gc = idx >> 4, icq = idx & 15;
        uint32_t hv[4], lv[4];
#pragma unroll
        for (int j = 0; j < 4; j++) {
            uint32_t a = sp[icq * 8 + 2 * j][gc];
            uint32_t bb = sp[icq * 8 + 2 * j + 1][gc];
            hv[j] = (a & 0xFFFFu) | (bb << 16);
            lv[j] = (a >> 16) | (bb & 0xFFFF0000u);
        }
        int icb = (ic0 >> 6) + (icq >> 3);          // plane within batch
        int pix = (gr + 2) * 68 + (gc + 2);
        size_t off = (((size_t)(b * 8 + icb) * 4624 + pix) << 6) + (icq & 7) * 8;
        *(int4*)(g_xta_h + off) = *(int4*)hv;
        *(int4*)(g_xta_l + off) = *(int4*)lv;
    }
}

// pack weights: klin = pos*512+ic, pre-swizzled SW128 smem tile layout
__global__ void __launch_bounds__(256) k_pack_Bsw(const float* __restrict__ cw) {
    const int oc = blockIdx.x;
    const float* src = cw + (size_t)oc * 4608;
#pragma unroll 2
    for (int it = 0; it < 18; it++) {
        int idx = it * 256 + threadIdx.x;   // = ic*9 + pos
        int ic = idx / 9, pos = idx - ic * 9;
        float v = src[idx];
        __nv_bfloat16 h = __float2bfloat16(v);
        float hf = __bfloat162float(h);
        __nv_bfloat16 l = __float2bfloat16(v - hf);
        int klin = pos * 512 + ic;
        int kc = klin >> 6, c = klin & 63;
        uint32_t off = ((uint32_t)(oc & 7) << 7) + ((uint32_t)c << 1);
        uint32_t sw = off ^ ((off >> 3) & 0x70);
        size_t addr = (((size_t)(kc * 512 + (oc & ~7))) << 7) + sw;  // bytes
        *(uint16_t*)((char*)g_bswh + addr) = __bfloat16_as_ushort(h);
        *(uint16_t*)((char*)g_bswl + addr) = __bfloat16_as_ushort(l);
    }
}

// ================= conv path A: tcgen05 cta_group::2 + TMA, 3-stage pipeline =================
// Cluster (2,1,1): M=256 across pair (128 px per CTA), N=256 with B split N/2 per CTA.
// K=4608 in 72 chunks of 64 (pos-major k).
// Stage per CTA: Ah[16K] Al[16K] Bh[16K] Bl[16K] = 64KB; three stages = 192KB.
#define STAGE_BYTES 65536
#define CONV_SMEM (3 * STAGE_BYTES + 1024)

__global__ void __launch_bounds__(256, 1) __cluster_dims__(2, 1, 1) k_conv_tc(
        const __grid_constant__ CUtensorMap mAh, const __grid_constant__ CUtensorMap mAl,
        const __grid_constant__ CUtensorMap mBh, const __grid_constant__ CUtensorMap mBl,
        const float* __restrict__ cb) {
#if HAS_TC
    extern __shared__ char dsm[];
    __shared__ uint32_t s_tmem[1];
    __shared__ __align__(8) unsigned long long s_full[3], s_mdone[3];
    __shared__ float s_d[256], s_b[256];

    const int tid = threadIdx.x;
    const int wid = tid >> 5, lid = tid & 31;
    const int m0 = blockIdx.x * 128;         // this CTA's 68-grid pixel base
    const int n0 = blockIdx.y * 256;
    const int b = blockIdx.z;
    const uint32_t rank = cluster_rank();    // = blockIdx.x & 1

    const uint32_t dsm0 = smem_u32(dsm);
    const uint32_t base = (dsm0 + 1023) & ~1023u;
    uint32_t full[3]  = { smem_u32(&s_full[0]),  smem_u32(&s_full[1]),  smem_u32(&s_full[2]) };
    uint32_t mdone[3] = { smem_u32(&s_mdone[0]), smem_u32(&s_mdone[1]), smem_u32(&s_mdone[2]) };

    if (wid == 0) { TC_ALLOC_CG2(smem_u32(s_tmem), 256); TC_RELINQ_CG2(); }
    if (tid == 0) {
        MBAR_INIT(full[0], 1); MBAR_INIT(full[1], 1); MBAR_INIT(full[2], 1);
        MBAR_INIT(mdone[0], 1); MBAR_INIT(mdone[1], 1); MBAR_INIT(mdone[2], 1);
        FENCE_ASYNC();
    }
    __syncthreads();
    CLUSTER_SYNC();   // peer barriers live before any cg2 TMA / multicast commit targets them
    const uint32_t tmem = s_tmem[0];

    uint64_t dAh[3], dAl[3], dBh[3], dBl[3];
#pragma unroll
    for (int s = 0; s < 3; s++) {
        uint32_t sb = base + s * STAGE_BYTES;
        dAh[s] = mk_desc(sb);
        dAl[s] = mk_desc(sb + 16384);
        dBh[s] = mk_desc(sb + 32768);
        dBl[s] = mk_desc(sb + 49152);
    }

    if (wid == 0) {
        uint32_t fph[3] = {0u, 0u, 0u}, mph[3] = {0u, 0u, 0u};

        // issue loads for chunk q into stage s; completions land on LEADER's full[s]
        auto issue = [&](int s, int q) {
            const int pos = q >> 3;
            const int icb = q & 7;
            const int kh = pos / 3, kw = pos - kh * 3;
            const uint32_t sb = base + s * STAGE_BYTES;
            if (rank == 0) MBAR_EXPECT_TX(full[s], 131072u);   // both CTAs' 64KB each
            int yA = (b * 8 + icb) * 4624 + m0 + kh * 68 + kw;
            tma2d_cg2(sb,         &mAh, 0, yA, full[s]);
            tma2d_cg2(sb + 16384, &mAl, 0, yA, full[s]);
            int yB = q * 512 + n0 + (int)rank * 128;           // B split: rank r -> oc rows [128r,128r+128)
            tma2d_cg2(sb + 32768, &mBh, 0, yB, full[s]);
            tma2d_cg2(sb + 49152, &mBl, 0, yB, full[s]);
        };

        if (elect_one()) { issue(0, 0); issue(1, 1); issue(2, 2); }

        int s = 0;
        for (int q = 0; q < 72; q++) {
            if (rank == 0) {
                mbar_wait(full[s], fph[s]); fph[s] ^= 1;
                if (elect_one()) {
#pragma unroll
                    for (int ks = 0; ks < 4; ks++) {
                        uint32_t en = (q > 0 || ks > 0) ? 1u : 0u;
                        uint64_t koff = (uint64_t)(ks * 2);
                        mma_f16_ss_cg2(tmem, dAh[s] + koff, dBh[s] + koff, IDESC_M256_N256, en);
                        mma_f16_ss_cg2(tmem, dAh[s] + koff, dBl[s] + koff, IDESC_M256_N256, 1u);
                        mma_f16_ss_cg2(tmem, dAl[s] + koff, dBh[s] + koff, IDESC_M256_N256, 1u);
                    }
                    TC_COMMIT_CG2_MC(mdone[s], 0x3);   // arrive on BOTH CTAs' mdone[s]
                }
            }
            // both ranks: stage s reusable only after mma(q) fully drained on the pair
            mbar_wait(mdone[s], mph[s]); mph[s] ^= 1;
            if (q + 3 < 72 && elect_one()) issue(s, q + 3);
            s = (s == 2) ? 0 : s + 1;
        }
    }
    __syncthreads();
    TC_FENCE_AFTER();

    s_d[tid] = g_demod[b * 512 + n0 + tid];
    s_b[tid] = cb[n0 + tid];
    __syncthreads();

    // epilogue: each CTA reads its own 128 TMEM rows x 256 cols
    const int sub = wid & 3;
    const int chalf = wid >> 2;
    const int mrow = sub * 32 + lid;       // 0..127
    const int opix = m0 + mrow;            // 68-grid pixel
    const int R = opix / 68, C = opix - R * 68;
    const bool valid = (R < 66) && (C < 66);
    float* dst = g_y66 + ((size_t)(b * 512 + n0)) * 4356 + (R * 66 + C);
    const uint32_t tbase = tmem + ((uint32_t)sub << 21) + (uint32_t)chalf * 128;

    for (int c0 = 0; c0 < 128; c0 += 32) {
        uint32_t rg[32];
        asm volatile("tcgen05.ld.sync.aligned.32x32b.x32.b32 "
            "{%0,%1,%2,%3,%4,%5,%6,%7,%8,%9,%10,%11,%12,%13,%14,%15,"
            "%16,%17,%18,%19,%20,%21,%22,%23,%24,%25,%26,%27,%28,%29,%30,%31}, [%32];"
            : "=r"(rg[0]), "=r"(rg[1]), "=r"(rg[2]), "=r"(rg[3]), "=r"(rg[4]), "=r"(rg[5]), "=r"(rg[6]), "=r"(rg[7]),
              "=r"(rg[8]), "=r"(rg[9]), "=r"(rg[10]), "=r"(rg[11]), "=r"(rg[12]), "=r"(rg[13]), "=r"(rg[14]), "=r"(rg[15]),
              "=r"(rg[16]), "=r"(rg[17]), "=r"(rg[18]), "=r"(rg[19]), "=r"(rg[20]), "=r"(rg[21]), "=r"(rg[22]), "=r"(rg[23]),
              "=r"(rg[24]), "=r"(rg[25]), "=r"(rg[26]), "=r"(rg[27]), "=r"(rg[28]), "=r"(rg[29]), "=r"(rg[30]), "=r"(rg[31])
            : "r"(tbase + c0));
        TC_WAIT_LD();
        if (valid) {
#pragma unroll
            for (int j = 0; j < 32; j++) {
                int n = chalf * 128 + c0 + j;
                dst[(size_t)n * 4356] = __uint_as_float(rg[j]) * s_d[n] + s_b[n];
            }
        }
    }
    TC_FENCE_BEFORE();
    __syncthreads();
    if (wid == 0) TC_DEALLOC_CG2(tmem, 256);
    CLUSTER_SYNC();   // no CTA exits while the pair's MMA/TMA could still touch its smem
#endif
}

// ================= conv path B: packed fp32x2 fallback =================
__global__ void __launch_bounds__(256) k_conv_f32x2(const float* __restrict__ x,
                                                    const float* __restrict__ cw,
                                                    const float* __restrict__ cb) {
#if !HAS_TC
    const int mblk = blockIdx.x, nblk = blockIdx.y, b = blockIdx.z;
    const int tid = threadIdx.x;
    const int tn = tid & 15;
    const int tm = tid >> 4;
    const int m0 = mblk * 128;
    const int row0 = m0 / 66;

    __shared__ __align__(8) float xsA[5][68];
    __shared__ __align__(8) float xsB[5][68];
    __shared__ unsigned long long ws2[9][64];

    const int mbase = m0 + tm * 8;
    int rrp[4], qqp[4];
#pragma unroll
    for (int p = 0; p < 4; p++) {
        int m = mbase + 2 * p;
        rrp[p] = m / 66 - row0;
        qqp[p] = m % 66;
    }

    unsigned long long acc[4][4];
#pragma unroll
    for (int p = 0; p < 4; p++)
#pragma unroll
        for (int j = 0; j < 4; j++) acc[p][j] = 0ull;

    const float* xb = x + (size_t)b * 512 * 4096;
    const float* mb = g_mult + b * 512;

    for (int ic = 0; ic < 512; ++ic) {
        const float mlt = __ldg(mb + ic);
        for (int idx = tid; idx < 340; idx += 256) {
            int sr = idx / 68, s = idx % 68;
            int gr = row0 + sr - 2, gc = s - 2;
            float v = 0.f;
            if ((unsigned)gr < 64u && (unsigned)gc < 64u)
                v = xb[ic * 4096 + gr * 64 + gc] * mlt;
            xsA[sr][s] = v;
            if (s) xsB[sr][s - 1] = v;
        }
        for (int idx = tid; idx < 576; idx += 256) {
            int oc = idx / 9, pos = idx % 9;
            uint32_t wv = __float_as_uint(cw[((size_t)(nblk * 64 + oc) * 512 + ic) * 9 + pos]);
            ws2[pos][oc] = (unsigned long long)wv | ((unsigned long long)wv << 32);
        }
        __syncthreads();
#pragma unroll
        for (int pos = 0; pos < 9; ++pos) {
            const int kh = pos / 3, kw = pos % 3;
            unsigned long long wv[4];
#pragma unroll
            for (int j = 0; j < 4; j++) wv[j] = ws2[pos][tn * 4 + j];
#pragma unroll
            for (int p = 0; p < 4; p++) {
                int rw = rrp[p] + kh;
                int s = qqp[p] + kw;
                unsigned long long xv = (kw & 1)
                    ? *(const unsigned long long*)&xsB[rw][s - 1]
                    : *(const unsigned long long*)&xsA[rw][s];
#pragma unroll
                for (int j = 0; j < 4; j++) fma2(acc[p][j], xv, wv[j]);
            }
        }
        __syncthreads();
    }

#pragma unroll
    for (int j = 0; j < 4; j++) {
        int oc = nblk * 64 + tn * 4 + j;
        float d  = g_demod[b * 512 + oc];
        float bs = cb[oc];
        float* dst = g_y66 + ((size_t)(b * 512 + oc)) * 4356;
#pragma unroll
        for (int p = 0; p < 4; p++) {
            unsigned long long a = acc[p][j];
            float lo = __uint_as_float((uint32_t)a);
            float hi = __uint_as_float((uint32_t)(a >> 32));
            int m = mbase + 2 * p;
            if (m < 4356)     dst[m]     = lo * d + bs;
            if (m + 1 < 4356) dst[m + 1] = hi * d + bs;
        }
    }
#endif
}

// ---------------- fused filtered leaky-ReLU ----------------
__global__ void __launch_bounds__(512) k_flrelu(const float* __restrict__ fu,
                                                const float* __restrict__ fd,
                                                float* __restrict__ out) {
    const int tile = blockIdx.x, ch = blockIdx.y, b = blockIdx.z;
    const int ox0 = (tile & 1) * 32, oy0 = (tile >> 1) * 32;
    const int tid = threadIdx.x;
    const int nthr = blockDim.x;

    __shared__ float sy[43][44];
    __shared__ float sv[43][76];
    __shared__ float sz[75][76];
    __shared__ float sfu[12], sfd[12];

    if (tid < 12) sfu[tid] = fu[tid] * 2.0f;
    else if (tid < 24) sfd[tid - 12] = fd[tid - 12];

    const float* ysrc = g_y66 + ((size_t)(b * 512 + ch)) * 4356;
    for (int idx = tid; idx < 43 * 43; idx += nthr) {
        int r = idx / 43, c = idx % 43;
        int gy = oy0 - 4 + r, gx = ox0 - 4 + c;
        float v = 0.f;
        if ((unsigned)gy < 66u && (unsigned)gx < 66u) v = ysrc[gy * 66 + gx];
        sy[r][c] = v;
    }
    __syncthreads();

    for (int idx = tid; idx < 43 * 75; idx += nthr) {
        int r = idx / 75, nx = idx % 75;
        int base = ((nx - 8) >> 1) + 4;
        int tsel = (nx & 1) ? 0 : 1;
        float a = 0.f;
#pragma unroll
        for (int t = 0; t < 6; t++) a += sfu[2 * t + tsel] * sy[r][base + t];
        sv[r][nx] = a;
    }
    __syncthreads();

    for (int idx = tid; idx < 75 * 75; idx += nthr) {
        int my = idx / 75, nx = idx % 75;
        int base = ((my - 8) >> 1) + 4;
        int tsel = (my & 1) ? 0 : 1;
        float a = 0.f;
#pragma unroll
        for (int t = 0; t < 6; t++) a += sfu[2 * t + tsel] * sv[base + t][nx];
        a = (a < 0.f ? 0.2f * a : a) * 1.4142135623730951f;
        a = fminf(fmaxf(a, -256.f), 256.f);
        sz[my][nx] = a;
    }
    __syncthreads();

    float* st = &sv[0][0];
    for (int idx = tid; idx < 75 * 32; idx += nthr) {
        int my = idx / 32, q = idx % 32;
        float a = 0.f;
#pragma unroll
        for (int k = 0; k < 12; k++) a += sfd[k] * sz[my][2 * q + k];
        st[my * 32 + q] = a;
    }
    __syncthreads();

    for (int idx = tid; idx < 32 * 32; idx += nthr) {
        int p = idx / 32, q = idx % 32;
        float a = 0.f;
#pragma unroll
        for (int k = 0; k < 12; k++) a += sfd[k] * st[(2 * p + k) * 32 + q];
        out[(((size_t)(b * 512 + ch)) * 64 + (oy0 + p)) * 64 + (ox0 + q)] = a;
    }
}

// ---------------- host: tensor map creation ----------------
typedef CUresult (*tmap_fn_t)(CUtensorMap*, CUtensorMapDataType, cuuint32_t, void*,
                              const cuuint64_t*, const cuuint64_t*, const cuuint32_t*, const cuuint32_t*,
                              CUtensorMapInterleave, CUtensorMapSwizzle, CUtensorMapL2promotion,
                              CUtensorMapFloatOOBfill);

static void make_map(tmap_fn_t fn, CUtensorMap* m, void* ptr, unsigned long long rows,
                     unsigned box_rows, CUtensorMapSwizzle sw) {
    cuuint64_t dims[2]    = { 128ull, rows };
    cuuint64_t strides[1] = { 128ull };
    cuuint32_t box[2]     = { 128u, box_rows };
    cuuint32_t es[2]      = { 1u, 1u };
    fn(m, CU_TENSOR_MAP_DATA_TYPE_UINT8, 2, ptr, dims, strides, box, es,
       CU_TENSOR_MAP_INTERLEAVE_NONE, sw, CU_TENSOR_MAP_L2_PROMOTION_L2_128B,
       CU_TENSOR_MAP_FLOAT_OOB_FILL_NONE);
}

// ---------------- launch ----------------
extern "C" void kernel_launch(void* const* d_in, const int* in_sizes, int n_in,
                              void* d_out, int out_size) {
    (void)in_sizes; (void)n_in; (void)out_size;
    const float* x    = (const float*)d_in[0];
    const float* w    = (const float*)d_in[1];
    const float* aw   = (const float*)d_in[2];
    const float* ab   = (const float*)d_in[3];
    const float* cw   = (const float*)d_in[4];
    const float* cb   = (const float*)d_in[5];
    const float* fu   = (const float*)d_in[6];
    const float* fd   = (const float*)d_in[7];
    const float* wavg = (const float*)d_in[8];
    float* out = (float*)d_out;

    cudaFuncSetAttribute(k_conv_tc, cudaFuncAttributeMaxDynamicSharedMemorySize, CONV_SMEM);

    // tensor maps
    tmap_fn_t fn = nullptr;
    cudaDriverEntryPointQueryResult qr;
#if CUDART_VERSION >= 12050
    cudaGetDriverEntryPointByVersion("cuTensorMapEncodeTiled", (void**)&fn, 12000,
                                     cudaEnableDefault, &qr);
#else
    cudaGetDriverEntryPoint("cuTensorMapEncodeTiled", (void**)&fn, cudaEnableDefault, &qr);
#endif
    void *pAh = nullptr, *pAl = nullptr, *pBh = nullptr, *pBl = nullptr;
    cudaGetSymbolAddress(&pAh, g_xta_h);
    cudaGetSymbolAddress(&pAl, g_xta_l);
    cudaGetSymbolAddress(&pBh, g_bswh);
    cudaGetSymbolAddress(&pBl, g_bswl);
    CUtensorMap mAh, mAl, mBh, mBl;
    make_map(fn, &mAh, pAh, 64ull * 4624, 128, CU_TENSOR_MAP_SWIZZLE_128B);
    make_map(fn, &mAl, pAl, 64ull * 4624, 128, CU_TENSOR_MAP_SWIZZLE_128B);
    make_map(fn, &mBh, pBh, 36864ull, 128, CU_TENSOR_MAP_SWIZZLE_NONE);
    make_map(fn, &mBl, pBl, 36864ull, 128, CU_TENSOR_MAP_SWIZZLE_NONE);

    k_zero_border<<<dim3(4624, 8), 64>>>();
    k_pack_Bsw<<<512, 256>>>(cw);
    k_reduce<<<2048, 256>>>(x, 8 * 512 * 64 * 64);
    k_finalize<<<1, 1024>>>(wavg, 1.0f / (8.f * 512.f * 64.f * 64.f));
    k_styles<<<16, 256>>>(w, aw, ab);
    k_S<<<1024, 256>>>(cw);
    k_demod<<<16, 256>>>();
    k_transpose<<<dim3(4, 64, 8), 256>>>(x);
    // exactly one of these two has a non-empty body per compiled arch:
    k_conv_tc<<<dim3(36, 2, 8), 256, CONV_SMEM>>>(mAh, mAl, mBh, mBl, cb);
    k_conv_f32x2<<<dim3(35, 8, 8), 256>>>(x, cw, cb);
    k_flrelu<<<dim3(4, 512, 8), 512>>>(fu, fd, out);
}

// round 17
// speedup vs baseline: 1.0811x; 1.0811x over previous
#include <cuda_runtime.h>
#include <cuda.h>
#include <cuda_bf16.h>
#include <math.h>
#include <stdint.h>

#if defined(__CUDA_ARCH__) && defined(__CUDA_ARCH_FEAT_SM103_ALL)
#define HAS_TC 1
#else
#define HAS_TC 0
#endif

// ---------------- scratch ----------------
static __device__ float g_y66[8 * 512 * 66 * 66];                      // conv output 71.4 MB
static __device__ __align__(1024) uint16_t g_xta_h[64 * 4624 * 64];    // [b*8+icb][pix68][64ic] hi bf16
static __device__ __align__(1024) uint16_t g_xta_l[64 * 4624 * 64];    // lo bf16
static __device__ __align__(1024) uint16_t g_bswh[72 * 512 * 64];      // weights pre-swizzled, pos-major k, hi
static __device__ __align__(1024) uint16_t g_bswl[72 * 512 * 64];      // lo
static __device__ float g_partials[2048];
static __device__ float g_inv[1];
static __device__ float g_styles[8 * 512];
static __device__ float g_mult[8 * 512];
static __device__ float g_S[512 * 512];
static __device__ float g_demod[8 * 512];

// ---------------- PTX helpers ----------------
__device__ __forceinline__ uint32_t smem_u32(const void* p) {
    uint32_t a;
    asm("{ .reg .u64 t; cvta.to.shared.u64 t, %1; cvt.u32.u64 %0, t; }" : "=r"(a) : "l"(p));
    return a;
}
__device__ __forceinline__ uint32_t elect_one() {
    uint32_t p;
    asm volatile("{\n\t.reg .pred p;\n\telect.sync _|p, 0xFFFFFFFF;\n\tselp.b32 %0, 1, 0, p;\n\t}" : "=r"(p));
    return p;
}
#define MBAR_INIT(mb, c)  asm volatile("mbarrier.init.shared.b64 [%0], %1;" :: "r"(mb), "r"(c) : "memory")
#define FENCE_ASYNC()     asm volatile("fence.proxy.async.shared::cta;" ::: "memory")
#define MBAR_EXPECT_TX(mb, bytes) \
    asm volatile("mbarrier.arrive.expect_tx.shared.b64 _, [%0], %1;" :: "r"(mb), "r"(bytes) : "memory")

__device__ __forceinline__ void mbar_wait(uint32_t mb, uint32_t parity) {
    uint32_t done;
    asm volatile("{\n\t.reg .pred p;\n\tmbarrier.try_wait.parity.acquire.cta.shared::cta.b64 p, [%1], %2;\n\tselp.b32 %0, 1, 0, p;\n\t}"
                 : "=r"(done) : "r"(mb), "r"(parity) : "memory");
    if (!done) {
        asm volatile("{\n\t.reg .pred P1;\n\tWL_%=:\n\tmbarrier.try_wait.parity.acquire.cta.shared::cta.b64 P1, [%0], %1, 0x989680;\n\t@P1 bra.uni WD_%=;\n\tbra.uni WL_%=;\n\tWD_%=:\n\t}"
                     :: "r"(mb), "r"(parity) : "memory");
    }
}

// packed fp32x2 FMA (fallback path)
__device__ __forceinline__ void fma2(unsigned long long& d, unsigned long long a, unsigned long long b) {
    asm("fma.rn.f32x2 %0, %1, %2, %0;" : "+l"(d) : "l"(a), "l"(b));
}

#if HAS_TC
#define TC_ALLOC(sm, n)   asm volatile("tcgen05.alloc.cta_group::1.sync.aligned.shared::cta.b32 [%0], %1;" :: "r"(sm), "r"(n) : "memory")
#define TC_DEALLOC(t, n)  asm volatile("tcgen05.dealloc.cta_group::1.sync.aligned.b32 %0, %1;" :: "r"(t), "r"(n))
#define TC_RELINQ()       asm volatile("tcgen05.relinquish_alloc_permit.cta_group::1.sync.aligned;")
#define TC_COMMIT(mb)     asm volatile("tcgen05.commit.cta_group::1.mbarrier::arrive::one.shared::cluster.b64 [%0];" :: "r"(mb) : "memory")
#define TC_FENCE_AFTER()  asm volatile("tcgen05.fence::after_thread_sync;" ::: "memory")
#define TC_FENCE_BEFORE() asm volatile("tcgen05.fence::before_thread_sync;" ::: "memory")
#define TC_WAIT_LD()      asm volatile("tcgen05.wait::ld.sync.aligned;" ::: "memory")
__device__ __forceinline__ void mma_f16_ss(uint32_t d, uint64_t a, uint64_t b, uint32_t idesc, uint32_t en) {
    asm volatile("{\n\t.reg .pred p;\n\tsetp.ne.u32 p, %4, 0;\n\t"
                 "tcgen05.mma.cta_group::1.kind::f16 [%0], %1, %2, %3, {%5, %5, %5, %5}, p;\n\t}"
                 :: "r"(d), "l"(a), "l"(b), "r"(idesc), "r"(en), "r"(0u) : "memory");
}
__device__ __forceinline__ void tma2d(uint32_t dst, const void* map, int x, int y, uint32_t mbar) {
    asm volatile("cp.async.bulk.tensor.2d.shared::cta.global.tile.mbarrier::complete_tx::bytes "
                 "[%0], [%1, {%2, %3}], [%4];"
                 :: "r"(dst), "l"(map), "r"(x), "r"(y), "r"(mbar) : "memory");
}
#endif

// SW128 K-major descriptor base: layout=2, version=1, SBO=64, LBO=1
__device__ __forceinline__ uint64_t mk_desc(uint32_t addr) {
    return ((uint64_t)2 << 61) | ((uint64_t)1 << 46) | ((uint64_t)64 << 32) | ((uint64_t)1 << 16)
         | (uint64_t)((addr >> 4) & 0x3FFF);
}
// idesc kind::f16: F32 accum | A=BF16 | B=BF16 | N=256 | M=128
#define IDESC_M128_N256 ((1u<<4) | (1u<<7) | (1u<<10) | (32u<<17) | (8u<<24))

// ---------------- launch 0: fused prep (zero borders + pack B + S) ----------------
__global__ void __launch_bounds__(256) k_prep1(const float* __restrict__ cw) {
    const int bx = blockIdx.x;
    const int tid = threadIdx.x;
    if (bx < 512) {
        // pack weights: klin = pos*512+ic, pre-swizzled SW128 smem tile layout
        const int oc = bx;
        const float* src = cw + (size_t)oc * 4608;
#pragma unroll 2
        for (int it = 0; it < 18; it++) {
            int idx = it * 256 + tid;      // = ic*9 + pos
            int ic = idx / 9, pos = idx - ic * 9;
            float v = src[idx];
            __nv_bfloat16 h = __float2bfloat16(v);
            float hf = __bfloat162float(h);
            __nv_bfloat16 l = __float2bfloat16(v - hf);
            int klin = pos * 512 + ic;
            int kc = klin >> 6, c = klin & 63;
            uint32_t off = ((uint32_t)(oc & 7) << 7) + ((uint32_t)c << 1);
            uint32_t sw = off ^ ((off >> 3) & 0x70);
            size_t addr = (((size_t)(kc * 512 + (oc & ~7))) << 7) + sw;
            *(uint16_t*)((char*)g_bswh + addr) = __bfloat16_as_ushort(h);
            *(uint16_t*)((char*)g_bswl + addr) = __bfloat16_as_ushort(l);
        }
    } else if (bx < 1536) {
        // S[o][i] = sum_k conv_w^2
        int idx = (bx - 512) * 256 + tid;
        const float* p = cw + (size_t)idx * 9;
        float s = 0.f;
#pragma unroll
        for (int k = 0; k < 9; k++) s += p[k] * p[k];
        g_S[idx] = s;
    } else {
        // zero borders: 4 (pix,b) jobs per block, 64 threads each
        int job = (bx - 1536) * 4 + (tid >> 6);
        int b = job / 4624, pix = job - b * 4624;
        int pr = pix / 68, pc = pix % 68;
        if (pr >= 2 && pr < 66 && pc >= 2 && pc < 66) return;
        int lane = tid & 63;
        int icb = lane >> 3, seg = lane & 7;
        size_t off = (((size_t)(b * 8 + icb) * 4624 + pix) << 6) + seg * 8;
        int4 z = make_int4(0, 0, 0, 0);
        *(int4*)(g_xta_h + off) = z;
        *(int4*)(g_xta_l + off) = z;
    }
}

// ---------------- launch 1-3 ----------------
__global__ void __launch_bounds__(256) k_reduce(const float* __restrict__ x, int n) {
    float s = 0.f;
    for (int i = blockIdx.x * blockDim.x + threadIdx.x; i < n; i += gridDim.x * blockDim.x) {
        float v = x[i]; s += v * v;
    }
    __shared__ float sm[256];
    sm[threadIdx.x] = s; __syncthreads();
    for (int o = 128; o > 0; o >>= 1) { if (threadIdx.x < o) sm[threadIdx.x] += sm[threadIdx.x + o]; __syncthreads(); }
    if (threadIdx.x == 0) g_partials[blockIdx.x] = sm[0];
}
__global__ void __launch_bounds__(1024) k_finalize(const float* __restrict__ w_avg, float inv_n) {
    __shared__ float sm[1024];
    float s = 0.f;
    for (int i = threadIdx.x; i < 2048; i += 1024) s += g_partials[i];
    sm[threadIdx.x] = s; __syncthreads();
    for (int o = 512; o > 0; o >>= 1) { if (threadIdx.x < o) sm[threadIdx.x] += sm[threadIdx.x + o]; __syncthreads(); }
    if (threadIdx.x == 0) {
        float mag = sm[0] * inv_n;
        float wn  = mag + 0.999f * (w_avg[0] - mag);
        g_inv[0]  = rsqrtf(wn);
    }
}
__global__ void __launch_bounds__(256) k_styles(const float* __restrict__ w, const float* __restrict__ aw,
                                                const float* __restrict__ ab) {
    int idx = blockIdx.x * 256 + threadIdx.x;
    int b = idx >> 9, i = idx & 511;
    const float* wr = w + b * 512;
    const float* ar = aw + i * 512;
    float s = 0.f;
    for (int j = 0; j < 512; j++) s += wr[j] * ar[j];
    s = s * 0.04419417382415922f + ab[i];
    g_styles[idx] = s;
    g_mult[idx]   = s * g_inv[0];
}

// ---------------- launch 4: fused transpose + demod ----------------
__global__ void __launch_bounds__(256) k_trans_demod(const float* __restrict__ x) {
    __shared__ uint32_t sp[128][65];
    const int bx = blockIdx.x;
    const int tid = threadIdx.x;
    if (bx >= 2048) {
        // demod d[b][o] = rsqrt(sum_i styles^2 * S[o][i] + 1e-8)
        int idx = (bx - 2048) * 256 + tid;
        int b = idx >> 9, o = idx & 511;
        const float* st = g_styles + b * 512;
        const float* Sr = g_S + o * 512;
        float s = 0.f;
        for (int i = 0; i < 512; i++) { float t = st[i]; s += t * t * Sr[i]; }
        g_demod[idx] = rsqrtf(s + 1e-8f);
        return;
    }
    // transpose + scale + split into [b*8+icb][pix][64ic] hi/lo planes
    const int ic0 = (bx & 3) << 7;
    const int gr = (bx >> 2) & 63;
    const int b = bx >> 8;
    const float* mb = g_mult + b * 512 + ic0;
    const float* xb = x + (((size_t)(b * 512 + ic0)) << 12) + (gr << 6);
#pragma unroll
    for (int it = 0; it < 32; it++) {
        int idx = it * 256 + tid;
        int icl = idx >> 6, gc = idx & 63;
        float v = xb[((size_t)icl << 12) + gc] * mb[icl];
        __nv_bfloat16 h = __float2bfloat16(v);
        float hf = __bfloat162float(h);
        __nv_bfloat16 l = __float2bfloat16(v - hf);
        sp[icl][gc] = (uint32_t)__bfloat16_as_ushort(h) | ((uint32_t)__bfloat16_as_ushort(l) << 16);
    }
    __syncthreads();
#pragma unroll
    for (int it = 0; it < 4; it++) {
        int idx = it * 256 + tid;
        int gc = idx >> 4, icq = idx & 15;
        uint32_t hv[4], lv[4];
#pragma unroll
        for (int j = 0; j < 4; j++) {
            uint32_t a = sp[icq * 8 + 2 * j][gc];
            uint32_t bb = sp[icq * 8 + 2 * j + 1][gc];
            hv[j] = (a & 0xFFFFu) | (bb << 16);
            lv[j] = (a >> 16) | (bb & 0xFFFF0000u);
        }
        int icb = (ic0 >> 6) + (icq >> 3);
        int pix = (gr + 2) * 68 + (gc + 2);
        size_t off = (((size_t)(b * 8 + icb) * 4624 + pix) << 6) + (icq & 7) * 8;
        *(int4*)(g_xta_h + off) = *(int4*)hv;
        *(int4*)(g_xta_l + off) = *(int4*)lv;
    }
}

// ================= launch 5: conv, tcgen05 + TMA, single stage, 2 CTAs/SM =================
// CTA: M=128 px (68-grid) x N=256 oc, K=4608 in 72 chunks of 64 (pos-major k).
// Stage: Ah[16K] Al[16K] Bh[32K] Bl[32K] = 96KB; ONE stage -> 2 CTAs/SM overlap in HW.
#define STAGE_BYTES 98304
#define CONV_SMEM (STAGE_BYTES + 1024)

__global__ void __launch_bounds__(256, 2) k_conv_tc(
        const __grid_constant__ CUtensorMap mAh, const __grid_constant__ CUtensorMap mAl,
        const __grid_constant__ CUtensorMap mBh, const __grid_constant__ CUtensorMap mBl,
        const float* __restrict__ cb) {
#if HAS_TC
    extern __shared__ char dsm[];
    __shared__ uint32_t s_tmem[1];
    __shared__ __align__(8) unsigned long long s_full[1], s_mdone[1];
    __shared__ float s_d[256], s_b[256];

    const int tid = threadIdx.x;
    const int wid = tid >> 5, lid = tid & 31;
    const int m0 = blockIdx.x * 128;         // 68-grid pixel base
    const int n0 = blockIdx.y * 256;
    const int b = blockIdx.z;

    const uint32_t dsm0 = smem_u32(dsm);
    const uint32_t base = (dsm0 + 1023) & ~1023u;
    const uint32_t full = smem_u32(&s_full[0]);
    const uint32_t mdone = smem_u32(&s_mdone[0]);

    if (wid == 0) { TC_ALLOC(smem_u32(s_tmem), 256); TC_RELINQ(); }
    if (tid == 0) {
        MBAR_INIT(full, 1);
        MBAR_INIT(mdone, 1);
        FENCE_ASYNC();
    }
    __syncthreads();
    const uint32_t tmem = s_tmem[0];

    const uint64_t dAh = mk_desc(base);
    const uint64_t dAl = mk_desc(base + 16384);
    const uint64_t dBh = mk_desc(base + 32768);
    const uint64_t dBl = mk_desc(base + 65536);

    if (wid == 0) {
        uint32_t fph = 0, mph = 0;

        auto issue = [&](int kc) {
            const int pos = kc >> 3;
            const int ic0 = (kc & 7) << 6;
            const int kh = pos / 3, kw = pos - kh * 3;
            MBAR_EXPECT_TX(full, (uint32_t)STAGE_BYTES);
            int yA = (b * 8 + (ic0 >> 6)) * 4624 + m0 + kh * 68 + kw;
            tma2d(base,         &mAh, 0, yA, full);
            tma2d(base + 16384, &mAl, 0, yA, full);
            int yB = kc * 512 + n0;
            tma2d(base + 32768, &mBh, 0, yB, full);
            tma2d(base + 65536, &mBl, 0, yB, full);
        };

        if (elect_one()) issue(0);

        for (int kc = 0; kc < 72; kc++) {
            mbar_wait(full, fph); fph ^= 1;
            if (elect_one()) {
#pragma unroll
                for (int ks = 0; ks < 4; ks++) {
                    uint32_t en = (kc > 0 || ks > 0) ? 1u : 0u;
                    uint64_t koff = (uint64_t)(ks * 2);
                    mma_f16_ss(tmem, dAh + koff, dBh + koff, IDESC_M128_N256, en);
                    mma_f16_ss(tmem, dAh + koff, dBl + koff, IDESC_M128_N256, 1u);
                    mma_f16_ss(tmem, dAl + koff, dBh + koff, IDESC_M128_N256, 1u);
                }
                TC_COMMIT(mdone);
            }
            mbar_wait(mdone, mph); mph ^= 1;
            if (kc + 1 < 72 && elect_one()) issue(kc + 1);
        }
    }
    __syncthreads();
    TC_FENCE_AFTER();

    s_d[tid] = g_demod[b * 512 + n0 + tid];
    s_b[tid] = cb[n0 + tid];
    __syncthreads();

    // epilogue: warps 0-3 rows (sub), warps 4-7 -> second 128-col half
    const int sub = wid & 3;
    const int chalf = wid >> 2;
    const int mrow = sub * 32 + lid;       // 0..127
    const int opix = m0 + mrow;            // 68-grid pixel
    const int R = opix / 68, C = opix - R * 68;
    const bool valid = (R < 66) && (C < 66);
    float* dst = g_y66 + ((size_t)(b * 512 + n0)) * 4356 + (R * 66 + C);
    const uint32_t tbase = tmem + ((uint32_t)sub << 21) + (uint32_t)chalf * 128;

    for (int c0 = 0; c0 < 128; c0 += 32) {
        uint32_t rg[32];
        asm volatile("tcgen05.ld.sync.aligned.32x32b.x32.b32 "
            "{%0,%1,%2,%3,%4,%5,%6,%7,%8,%9,%10,%11,%12,%13,%14,%15,"
            "%16,%17,%18,%19,%20,%21,%22,%23,%24,%25,%26,%27,%28,%29,%30,%31}, [%32];"
            : "=r"(rg[0]), "=r"(rg[1]), "=r"(rg[2]), "=r"(rg[3]), "=r"(rg[4]), "=r"(rg[5]), "=r"(rg[6]), "=r"(rg[7]),
              "=r"(rg[8]), "=r"(rg[9]), "=r"(rg[10]), "=r"(rg[11]), "=r"(rg[12]), "=r"(rg[13]), "=r"(rg[14]), "=r"(rg[15]),
              "=r"(rg[16]), "=r"(rg[17]), "=r"(rg[18]), "=r"(rg[19]), "=r"(rg[20]), "=r"(rg[21]), "=r"(rg[22]), "=r"(rg[23]),
              "=r"(rg[24]), "=r"(rg[25]), "=r"(rg[26]), "=r"(rg[27]), "=r"(rg[28]), "=r"(rg[29]), "=r"(rg[30]), "=r"(rg[31])
            : "r"(tbase + c0));
        TC_WAIT_LD();
        if (valid) {
#pragma unroll
            for (int j = 0; j < 32; j++) {
                int n = chalf * 128 + c0 + j;
                dst[(size_t)n * 4356] = __uint_as_float(rg[j]) * s_d[n] + s_b[n];
            }
        }
    }
    TC_FENCE_BEFORE();
    __syncthreads();
    if (wid == 0) TC_DEALLOC(tmem, 256);
#endif
}

// ================= conv path B: packed fp32x2 fallback =================
__global__ void __launch_bounds__(256) k_conv_f32x2(const float* __restrict__ x,
                                                    const float* __restrict__ cw,
                                                    const float* __restrict__ cb) {
#if !HAS_TC
    const int mblk = blockIdx.x, nblk = blockIdx.y, b = blockIdx.z;
    const int tid = threadIdx.x;
    const int tn = tid & 15;
    const int tm = tid >> 4;
    const int m0 = mblk * 128;
    const int row0 = m0 / 66;

    __shared__ __align__(8) float xsA[5][68];
    __shared__ __align__(8) float xsB[5][68];
    __shared__ unsigned long long ws2[9][64];

    const int mbase = m0 + tm * 8;
    int rrp[4], qqp[4];
#pragma unroll
    for (int p = 0; p < 4; p++) {
        int m = mbase + 2 * p;
        rrp[p] = m / 66 - row0;
        qqp[p] = m % 66;
    }

    unsigned long long acc[4][4];
#pragma unroll
    for (int p = 0; p < 4; p++)
#pragma unroll
        for (int j = 0; j < 4; j++) acc[p][j] = 0ull;

    const float* xb = x + (size_t)b * 512 * 4096;
    const float* mb = g_mult + b * 512;

    for (int ic = 0; ic < 512; ++ic) {
        const float mlt = __ldg(mb + ic);
        for (int idx = tid; idx < 340; idx += 256) {
            int sr = idx / 68, s = idx % 68;
            int gr = row0 + sr - 2, gc = s - 2;
            float v = 0.f;
            if ((unsigned)gr < 64u && (unsigned)gc < 64u)
                v = xb[ic * 4096 + gr * 64 + gc] * mlt;
            xsA[sr][s] = v;
            if (s) xsB[sr][s - 1] = v;
        }
        for (int idx = tid; idx < 576; idx += 256) {
            int oc = idx / 9, pos = idx % 9;
            uint32_t wv = __float_as_uint(cw[((size_t)(nblk * 64 + oc) * 512 + ic) * 9 + pos]);
            ws2[pos][oc] = (unsigned long long)wv | ((unsigned long long)wv << 32);
        }
        __syncthreads();
#pragma unroll
        for (int pos = 0; pos < 9; ++pos) {
            const int kh = pos / 3, kw = pos % 3;
            unsigned long long wv[4];
#pragma unroll
            for (int j = 0; j < 4; j++) wv[j] = ws2[pos][tn * 4 + j];
#pragma unroll
            for (int p = 0; p < 4; p++) {
                int rw = rrp[p] + kh;
                int s = qqp[p] + kw;
                unsigned long long xv = (kw & 1)
                    ? *(const unsigned long long*)&xsB[rw][s - 1]
                    : *(const unsigned long long*)&xsA[rw][s];
#pragma unroll
                for (int j = 0; j < 4; j++) fma2(acc[p][j], xv, wv[j]);
            }
        }
        __syncthreads();
    }

#pragma unroll
    for (int j = 0; j < 4; j++) {
        int oc = nblk * 64 + tn * 4 + j;
        float d  = g_demod[b * 512 + oc];
        float bs = cb[oc];
        float* dst = g_y66 + ((size_t)(b * 512 + oc)) * 4356;
#pragma unroll
        for (int p = 0; p < 4; p++) {
            unsigned long long a = acc[p][j];
            float lo = __uint_as_float((uint32_t)a);
            float hi = __uint_as_float((uint32_t)(a >> 32));
            int m = mbase + 2 * p;
            if (m < 4356)     dst[m]     = lo * d + bs;
            if (m + 1 < 4356) dst[m + 1] = hi * d + bs;
        }
    }
#endif
}

// ---------------- fused filtered leaky-ReLU ----------------
__global__ void __launch_bounds__(512) k_flrelu(const float* __restrict__ fu,
                                                const float* __restrict__ fd,
                                                float* __restrict__ out) {
    const int tile = blockIdx.x, ch = blockIdx.y, b = blockIdx.z;
    const int ox0 = (tile & 1) * 32, oy0 = (tile >> 1) * 32;
    const int tid = threadIdx.x;
    const int nthr = blockDim.x;

    __shared__ float sy[43][44];
    __shared__ float sv[43][76];
    __shared__ float sz[75][76];
    __shared__ float sfu[12], sfd[12];

    if (tid < 12) sfu[tid] = fu[tid] * 2.0f;
    else if (tid < 24) sfd[tid - 12] = fd[tid - 12];

    const float* ysrc = g_y66 + ((size_t)(b * 512 + ch)) * 4356;
    for (int idx = tid; idx < 43 * 43; idx += nthr) {
        int r = idx / 43, c = idx % 43;
        int gy = oy0 - 4 + r, gx = ox0 - 4 + c;
        float v = 0.f;
        if ((unsigned)gy < 66u && (unsigned)gx < 66u) v = ysrc[gy * 66 + gx];
        sy[r][c] = v;
    }
    __syncthreads();

    for (int idx = tid; idx < 43 * 75; idx += nthr) {
        int r = idx / 75, nx = idx % 75;
        int base = ((nx - 8) >> 1) + 4;
        int tsel = (nx & 1) ? 0 : 1;
        float a = 0.f;
#pragma unroll
        for (int t = 0; t < 6; t++) a += sfu[2 * t + tsel] * sy[r][base + t];
        sv[r][nx] = a;
    }
    __syncthreads();

    for (int idx = tid; idx < 75 * 75; idx += nthr) {
        int my = idx / 75, nx = idx % 75;
        int base = ((my - 8) >> 1) + 4;
        int tsel = (my & 1) ? 0 : 1;
        float a = 0.f;
#pragma unroll
        for (int t = 0; t < 6; t++) a += sfu[2 * t + tsel] * sv[base + t][nx];
        a = (a < 0.f ? 0.2f * a : a) * 1.4142135623730951f;
        a = fminf(fmaxf(a, -256.f), 256.f);
        sz[my][nx] = a;
    }
    __syncthreads();

    float* st = &sv[0][0];
    for (int idx = tid; idx < 75 * 32; idx += nthr) {
        int my = idx / 32, q = idx % 32;
        float a = 0.f;
#pragma unroll
        for (int k = 0; k < 12; k++) a += sfd[k] * sz[my][2 * q + k];
        st[my * 32 + q] = a;
    }
    __syncthreads();

    for (int idx = tid; idx < 32 * 32; idx += nthr) {
        int p = idx / 32, q = idx % 32;
        float a = 0.f;
#pragma unroll
        for (int k = 0; k < 12; k++) a += sfd[k] * st[(2 * p + k) * 32 + q];
        out[(((size_t)(b * 512 + ch)) * 64 + (oy0 + p)) * 64 + (ox0 + q)] = a;
    }
}

// ---------------- host: tensor map creation ----------------
typedef CUresult (*tmap_fn_t)(CUtensorMap*, CUtensorMapDataType, cuuint32_t, void*,
                              const cuuint64_t*, const cuuint64_t*, const cuuint32_t*, const cuuint32_t*,
                              CUtensorMapInterleave, CUtensorMapSwizzle, CUtensorMapL2promotion,
                              CUtensorMapFloatOOBfill);

static void make_map(tmap_fn_t fn, CUtensorMap* m, void* ptr, unsigned long long rows,
                     unsigned box_rows, CUtensorMapSwizzle sw) {
    cuuint64_t dims[2]    = { 128ull, rows };
    cuuint64_t strides[1] = { 128ull };
    cuuint32_t box[2]     = { 128u, box_rows };
    cuuint32_t es[2]      = { 1u, 1u };
    fn(m, CU_TENSOR_MAP_DATA_TYPE_UINT8, 2, ptr, dims, strides, box, es,
       CU_TENSOR_MAP_INTERLEAVE_NONE, sw, CU_TENSOR_MAP_L2_PROMOTION_L2_128B,
       CU_TENSOR_MAP_FLOAT_OOB_FILL_NONE);
}

// ---------------- launch ----------------
extern "C" void kernel_launch(void* const* d_in, const int* in_sizes, int n_in,
                              void* d_out, int out_size) {
    (void)in_sizes; (void)n_in; (void)out_size;
    const float* x    = (const float*)d_in[0];
    const float* w    = (const float*)d_in[1];
    const float* aw   = (const float*)d_in[2];
    const float* ab   = (const float*)d_in[3];
    const float* cw   = (const float*)d_in[4];
    const float* cb   = (const float*)d_in[5];
    const float* fu   = (const float*)d_in[6];
    const float* fd   = (const float*)d_in[7];
    const float* wavg = (const float*)d_in[8];
    float* out = (float*)d_out;

    cudaFuncSetAttribute(k_conv_tc, cudaFuncAttributeMaxDynamicSharedMemorySize, CONV_SMEM);

    // tensor maps
    tmap_fn_t fn = nullptr;
    cudaDriverEntryPointQueryResult qr;
#if CUDART_VERSION >= 12050
    cudaGetDriverEntryPointByVersion("cuTensorMapEncodeTiled", (void**)&fn, 12000,
                                     cudaEnableDefault, &qr);
#else
    cudaGetDriverEntryPoint("cuTensorMapEncodeTiled", (void**)&fn, cudaEnableDefault, &qr);
#endif
    void *pAh = nullptr, *pAl = nullptr, *pBh = nullptr, *pBl = nullptr;
    cudaGetSymbolAddress(&pAh, g_xta_h);
    cudaGetSymbolAddress(&pAl, g_xta_l);
    cudaGetSymbolAddress(&pBh, g_bswh);
    cudaGetSymbolAddress(&pBl, g_bswl);
    CUtensorMap mAh, mAl, mBh, mBl;
    make_map(fn, &mAh, pAh, 64ull * 4624, 128, CU_TENSOR_MAP_SWIZZLE_128B);
    make_map(fn, &mAl, pAl, 64ull * 4624, 128, CU_TENSOR_MAP_SWIZZLE_128B);
    make_map(fn, &mBh, pBh, 36864ull, 256, CU_TENSOR_MAP_SWIZZLE_NONE);
    make_map(fn, &mBl, pBl, 36864ull, 256, CU_TENSOR_MAP_SWIZZLE_NONE);

    // launch order arranged so ncu (-s 5 -c 1) captures k_conv_tc (launch index 5)
    k_prep1<<<10784, 256>>>(cw);                 // 0: zero borders + pack B + S
    k_reduce<<<2048, 256>>>(x, 8 * 512 * 64 * 64);   // 1
    k_finalize<<<1, 1024>>>(wavg, 1.0f / (8.f * 512.f * 64.f * 64.f));  // 2
    k_styles<<<16, 256>>>(w, aw, ab);            // 3
    k_trans_demod<<<2064, 256>>>(x);             // 4: transpose + demod
    k_conv_tc<<<dim3(36, 2, 8), 256, CONV_SMEM>>>(mAh, mAl, mBh, mBl, cb);  // 5 <- profiled
    k_conv_f32x2<<<dim3(35, 8, 8), 256>>>(x, cw, cb);  // 6 (empty on sm_103a)
    k_flrelu<<<dim3(4, 512, 8), 512>>>(fu, fd, out);   // 7
}